// round 16
// baseline (speedup 1.0000x reference)
#include <cuda_runtime.h>
#include <cuda_bf16.h>

#define BATCH 32
#define NAG   6
#define KS    256
#define QS    256
#define CHW   (512*32*32)       /* 524288 floats per (b,n) slab */
#define V4PB  (CHW/4)           /* 131072 float4 per (b,n) slab */
#define CHUNKS 8                /* attn kk-chunks per batch (32 rows each) */

typedef unsigned long long u64;

// Scratch (allocation-free rule: __device__ globals). Counters reset in the
// finalizer so every graph replay starts from identical state. All attn
// stores happen before the PDL trigger; wsum reads them only after
// cudaGridDependencySynchronize(), so plain loads are coherent there.
__device__ float        g_attn[BATCH * NAG];
__device__ u64          g_pack[BATCH];       // hi32: 1..6 = n0+1, 7 = multi
                                             // lo32: float bits of w[n0]
__device__ float        g_score[BATCH * NAG];
__device__ unsigned int g_cnt[BATCH];

// ---------------------------------------------------------------------------
// Kernel 1: attention. grid = 256 blocks (8 chunks per batch), 256 threads.
// Identical to the R15 version, plus a PDL trigger as the last instruction.
// ---------------------------------------------------------------------------
__global__ void __launch_bounds__(256)
attn_kernel(const float* __restrict__ q,
            const float* __restrict__ k,
            const float* __restrict__ W,
            const float* __restrict__ bias,
            float* __restrict__ out_attn,
            int write_attn) {
    const int bid    = blockIdx.x;
    const int ab     = bid >> 3;
    const int kkbase = (bid & 7) << 5;
    const int t      = threadIdx.x;
    const int wid    = t >> 5, lane = t & 31;

    __shared__ float4 sq4[QS / 4];
    __shared__ float  squery[32];

    // prefetch this warp's k element (overlaps the q/W loads below)
    float kval = 0.0f;
    if (wid < NAG)
        kval = k[(ab * NAG + wid) * KS + kkbase + lane];

    if (t < QS / 4) sq4[t] = ((const float4*)(q + ab * QS))[t];
    __syncthreads();

    // warp `wid` computes 4 query rows, 2 at a time
    {
        const int r0 = kkbase + (wid << 2);
        const float4 q0 = sq4[lane], q1 = sq4[lane + 32];
        #pragma unroll
        for (int h = 0; h < 2; h++) {
            const int ra = r0 + 2 * h;
            const float4* wa = (const float4*)(W + ra * QS);
            const float4* wb = (const float4*)(W + (ra + 1) * QS);
            float4 a0 = wa[lane], a1 = wa[lane + 32];
            float4 b0 = wb[lane], b1 = wb[lane + 32];
            float sa = a0.x * q0.x + a0.y * q0.y + a0.z * q0.z + a0.w * q0.w
                     + a1.x * q1.x + a1.y * q1.y + a1.z * q1.z + a1.w * q1.w;
            float sb = b0.x * q0.x + b0.y * q0.y + b0.z * q0.z + b0.w * q0.w
                     + b1.x * q1.x + b1.y * q1.y + b1.z * q1.z + b1.w * q1.w;
            #pragma unroll
            for (int o = 16; o; o >>= 1) {
                sa += __shfl_xor_sync(0xffffffffu, sa, o);
                sb += __shfl_xor_sync(0xffffffffu, sb, o);
            }
            if (lane == 0) {
                squery[(wid << 2) + 2 * h]     = sa + bias[ra];
                squery[(wid << 2) + 2 * h + 1] = sb + bias[ra + 1];
            }
        }
    }
    __syncthreads();

    // 6 warps -> partial agent scores (k already in registers)
    if (wid < NAG) {
        float p = kval * squery[lane];
        #pragma unroll
        for (int o = 16; o; o >>= 1) p += __shfl_xor_sync(0xffffffffu, p, o);
        if (lane == 0) atomicAdd(&g_score[ab * NAG + wid], p);
    }

    __threadfence();
    if (t == 0 && atomicAdd(&g_cnt[ab], 1u) == CHUNKS - 1) {
        __threadfence();                      // acquire all partials
        float z[NAG], zs[NAG];
        #pragma unroll
        for (int n = 0; n < NAG; n++) {
            z[n] = g_score[ab * NAG + n];
            zs[n] = z[n];
            g_score[ab * NAG + n] = 0.0f;     // reset for next replay
        }
        g_cnt[ab] = 0u;
        #pragma unroll
        for (int i = 1; i < NAG; i++) {       // insertion sort, descending
            float key = zs[i]; int j = i - 1;
            while (j >= 0 && zs[j] < key) { zs[j + 1] = zs[j]; j--; }
            zs[j + 1] = key;
        }
        float cs[NAG], run = 0.f;
        #pragma unroll
        for (int r = 0; r < NAG; r++) { run += zs[r]; cs[r] = run; }
        int kk = 0;
        #pragma unroll
        for (int r = 1; r <= NAG; r++)
            if (1.0f + (float)r * zs[r - 1] > cs[r - 1]) kk++;
        const float tau = (cs[kk - 1] - 1.0f) / (float)kk;

        int   nz = 0, n0 = 0;
        float w0 = 0.0f;
        #pragma unroll
        for (int n = 0; n < NAG; n++) {
            float p = fmaxf(z[n] - tau, 0.0f);
            g_attn[ab * NAG + n] = p;
            if (write_attn) out_attn[ab * NAG + n] = p;
            if (p != 0.0f) { if (nz == 0) { n0 = n; w0 = p; } nz++; }
        }
        const unsigned code = (nz == 1) ? (unsigned)(n0 + 1) : 7u;
        g_pack[ab] = ((u64)code << 32) | (u64)__float_as_uint(w0);
    }

    // PDL: allow the dependent wsum grid to proceed. All of this block's
    // stores are program-order before the trigger.
    cudaTriggerProgrammaticLaunchCompletion();
}

// ---------------------------------------------------------------------------
// Kernel 2: weighted sum. grid = 2048 x 256, tile = 2048 float4 per block.
// Launched with PDL: resident while attn still runs; first syncs on the
// dependency, then reads g_pack with plain loads (visibility guaranteed).
// Dominant path (k==1): accumulator-free 8x float4 scale-copy.
// Rare path (k>=2): two 4-accumulator halves over the 6 agents.
// ---------------------------------------------------------------------------
__global__ void __launch_bounds__(256)
wsum_kernel(const float* __restrict__ v, float* __restrict__ out) {
    const int bid  = blockIdx.x;
    const int t    = threadIdx.x;
    const int b    = bid >> 6;                        // 64 blocks/batch
    const int base = ((bid & 63) << 11) + t;          // float4 idx in slab

    // address math overlaps the dependency wait
    const float4* vslab = (const float4*)v + b * (NAG * V4PB);
    float4*       ob    = (float4*)out    + (b * V4PB + base);

    cudaGridDependencySynchronize();                  // wait for attn grid

    const u64 pk   = g_pack[b];
    const int code = (int)(pk >> 32);

    if (code <= NAG) {
        // ---- dominant: single nonzero agent -> scale-copy, MLP=8 ---------
        const float w = __uint_as_float((unsigned)pk);
        const float4* p = vslab + ((code - 1) * V4PB + base);
        float4 x[8];
        #pragma unroll
        for (int i = 0; i < 8; i++) x[i] = __ldcs(p + (i << 8));
        #pragma unroll
        for (int i = 0; i < 8; i++) {
            float4 r;
            r.x = w * x[i].x; r.y = w * x[i].y;
            r.z = w * x[i].z; r.w = w * x[i].w;
            __stcs(ob + (i << 8), r);
        }
    } else {
        // ---- rare: multi-agent accumulate, two halves of 4 ----------------
        float sw[NAG];
        #pragma unroll
        for (int n = 0; n < NAG; n++) sw[n] = g_attn[b * NAG + n];
        #pragma unroll
        for (int h = 0; h < 2; h++) {
            const int off = h << 10;                  // 0 or 1024 float4
            float4 acc0 = make_float4(0.f, 0.f, 0.f, 0.f);
            float4 acc1 = acc0, acc2 = acc0, acc3 = acc0;
            #pragma unroll
            for (int n = 0; n < NAG; n++) {
                const float w = sw[n];
                if (w != 0.0f) {                      // block-uniform branch
                    const float4* p = vslab + (n * V4PB + base + off);
                    float4 x0 = __ldcs(p);
                    float4 x1 = __ldcs(p + 256);
                    float4 x2 = __ldcs(p + 512);
                    float4 x3 = __ldcs(p + 768);
                    acc0.x = fmaf(w, x0.x, acc0.x); acc0.y = fmaf(w, x0.y, acc0.y);
                    acc0.z = fmaf(w, x0.z, acc0.z); acc0.w = fmaf(w, x0.w, acc0.w);
                    acc1.x = fmaf(w, x1.x, acc1.x); acc1.y = fmaf(w, x1.y, acc1.y);
                    acc1.z = fmaf(w, x1.z, acc1.z); acc1.w = fmaf(w, x1.w, acc1.w);
                    acc2.x = fmaf(w, x2.x, acc2.x); acc2.y = fmaf(w, x2.y, acc2.y);
                    acc2.z = fmaf(w, x2.z, acc2.z); acc2.w = fmaf(w, x2.w, acc2.w);
                    acc3.x = fmaf(w, x3.x, acc3.x); acc3.y = fmaf(w, x3.y, acc3.y);
                    acc3.z = fmaf(w, x3.z, acc3.z); acc3.w = fmaf(w, x3.w, acc3.w);
                }
            }
            __stcs(ob + off,       acc0);
            __stcs(ob + off + 256, acc1);
            __stcs(ob + off + 512, acc2);
            __stcs(ob + off + 768, acc3);
        }
    }
}

// ---------------------------------------------------------------------------
extern "C" void kernel_launch(void* const* d_in, const int* in_sizes, int n_in,
                              void* d_out, int out_size) {
    const float* q    = (const float*)d_in[0];
    const float* k    = (const float*)d_in[1];
    const float* v    = (const float*)d_in[2];
    const float* W    = (const float*)d_in[3];
    const float* bias = (const float*)d_in[4];

    float* out = (float*)d_out;
    const long long out_main = (long long)BATCH * CHW;        // 16777216
    const int write_attn = (out_size >= out_main + BATCH * NAG) ? 1 : 0;
    float* out_attn = out + out_main;

    attn_kernel<<<BATCH * CHUNKS, 256>>>(q, k, W, bias, out_attn, write_attn);

    // wsum with programmatic dependent launch: becomes resident while attn
    // runs; its blocks block in cudaGridDependencySynchronize() until attn's
    // triggers fire. Falls back to normal stream ordering if unsupported.
    cudaLaunchConfig_t cfg = {};
    cfg.gridDim  = dim3((BATCH * V4PB) / (256 * 8), 1, 1);    // 2048
    cfg.blockDim = dim3(256, 1, 1);
    cfg.dynamicSmemBytes = 0;
    cfg.stream = 0;
    cudaLaunchAttribute attrs[1];
    attrs[0].id = cudaLaunchAttributeProgrammaticStreamSerialization;
    attrs[0].val.programmaticStreamSerializationAllowed = 1;
    cfg.attrs = attrs;
    cfg.numAttrs = 1;
    cudaLaunchKernelEx(&cfg, wsum_kernel, v, out);
}